// round 5
// baseline (speedup 1.0000x reference)
#include <cuda_runtime.h>
#include <cuda_bf16.h>
#include <cstdint>

#define NN 50000
#define NE 600000
#define NPAD 50176   // NN padded past grid coverage (50048); pad rows stay zero

// ---------------- device-global scratch ------------------------------------
__device__ int   g_deg[NN];
__device__ int   g_off[NN];
__device__ int   g_pos[NN];
__device__ int   g_ctr;
__device__ int   g_esrc[NE];
__device__ float g_inv[NN];
__device__ __nv_bfloat16 g_ah[NPAD * 256];
__device__ __nv_bfloat16 g_al[NPAD * 256];
__device__ __nv_bfloat16 g_wh1[256 * 256], g_wl1[256 * 256];
__device__ __nv_bfloat16 g_wh2[256 * 256], g_wl2[256 * 256];
__device__ float g_y[NN * 256];

// ---------------- small helpers --------------------------------------------
__device__ __forceinline__ uint32_t smem_u32(const void* p) {
    return (uint32_t)__cvta_generic_to_shared(p);
}
__device__ __forceinline__ void cp16(uint32_t dst, const void* src) {
    asm volatile("cp.async.cg.shared.global [%0], [%1], 16;" :: "r"(dst), "l"(src));
}
__device__ __forceinline__ void cp_commit() {
    asm volatile("cp.async.commit_group;");
}
template <int N> __device__ __forceinline__ void cp_wait() {
    asm volatile("cp.async.wait_group %0;" :: "n"(N));
}
__device__ __forceinline__ void ldm_x4(uint32_t* r, uint32_t addr) {
    asm volatile("ldmatrix.sync.aligned.m8n8.x4.shared.b16 {%0,%1,%2,%3}, [%4];"
                 : "=r"(r[0]), "=r"(r[1]), "=r"(r[2]), "=r"(r[3]) : "r"(addr));
}
__device__ __forceinline__ void mma_bf16(float* c, const uint32_t* a, const uint32_t* b) {
    asm volatile("mma.sync.aligned.m16n8k16.row.col.f32.bf16.bf16.f32 "
                 "{%0,%1,%2,%3}, {%4,%5,%6,%7}, {%8,%9}, {%0,%1,%2,%3};"
                 : "+f"(c[0]), "+f"(c[1]), "+f"(c[2]), "+f"(c[3])
                 : "r"(a[0]), "r"(a[1]), "r"(a[2]), "r"(a[3]), "r"(b[0]), "r"(b[1]));
}
__device__ __forceinline__ void bf16_split(float x, __nv_bfloat16& h, __nv_bfloat16& l) {
    h = __float2bfloat16(x);
    l = __float2bfloat16(x - __bfloat162float(h));
}

// ---------------- init: zero degree + counter, split weights (fused) --------
__global__ void gs_init(const float* __restrict__ W1l, const float* __restrict__ W1r,
                        const float* __restrict__ W2l, const float* __restrict__ W2r) {
    int i = blockIdx.x * blockDim.x + threadIdx.x;
    if (i < NN) g_deg[i] = 0;
    if (i == 0) g_ctr = 0;
    if (i < 65536) {
        int n = i >> 8, k = i & 255;
        float w = (k < 128) ? W1l[n * 128 + k] : W1r[n * 128 + (k - 128)];
        __nv_bfloat16 h, l;
        bf16_split(w, h, l);
        g_wh1[i] = h; g_wl1[i] = l;
    } else if (i < 131072) {
        int j = i - 65536;
        int n = j >> 8, k = j & 255;
        float w = (n < 128) ? W2l[n * 256 + k] : W2r[(n - 128) * 256 + k];
        __nv_bfloat16 h, l;
        bf16_split(w, h, l);
        g_wh2[j] = h; g_wl2[j] = l;
    }
}

// ---------------- histogram: 4 edges/thread ---------------------------------
__global__ void gs_hist(const int* __restrict__ ei) {
    int e = (blockIdx.x * blockDim.x + threadIdx.x) * 4;
    if (e >= NE) return;
    int4 d = *(const int4*)(ei + NE + e);
    atomicAdd(&g_deg[d.x], 1);
    atomicAdd(&g_deg[d.y], 1);
    atomicAdd(&g_deg[d.z], 1);
    atomicAdd(&g_deg[d.w], 1);
}

// warp-aggregated offset assignment (segment order arbitrary)
__global__ void gs_offs() {
    int n = blockIdx.x * blockDim.x + threadIdx.x;
    int lane = threadIdx.x & 31;
    int d = (n < NN) ? g_deg[n] : 0;
    int s = d;
    #pragma unroll
    for (int o = 1; o < 32; o <<= 1) {
        int t = __shfl_up_sync(0xffffffffu, s, o);
        if (lane >= o) s += t;
    }
    int tot = __shfl_sync(0xffffffffu, s, 31);
    int base = 0;
    if (lane == 0) base = atomicAdd(&g_ctr, tot);
    base = __shfl_sync(0xffffffffu, base, 0);
    if (n < NN) {
        int o = base + s - d;
        g_off[n] = o;
        g_pos[n] = o;
    }
}

// ---------------- fill: 4 edges/thread --------------------------------------
__global__ void gs_fill(const int* __restrict__ ei) {
    int e = (blockIdx.x * blockDim.x + threadIdx.x) * 4;
    if (e >= NE) return;
    int4 s = *(const int4*)(ei + e);
    int4 d = *(const int4*)(ei + NE + e);
    int p0 = atomicAdd(&g_pos[d.x], 1);
    int p1 = atomicAdd(&g_pos[d.y], 1);
    int p2 = atomicAdd(&g_pos[d.z], 1);
    int p3 = atomicAdd(&g_pos[d.w], 1);
    g_esrc[p0] = s.x;
    g_esrc[p1] = s.y;
    g_esrc[p2] = s.z;
    g_esrc[p3] = s.w;
}

// ---------------- gather 1: mean(feat[nbrs]) + own feat -> split bf16 A ------
__global__ void gs_gather1(const float* __restrict__ feat) {
    int t = blockIdx.x * blockDim.x + threadIdx.x;
    int n = t >> 5;
    if (n >= NN) return;
    int lane = t & 31;
    int start = g_off[n], deg = g_deg[n];

    float4 acc = make_float4(0.f, 0.f, 0.f, 0.f);
    int i = 0;
    for (; i + 4 <= deg; i += 4) {
        int s0 = g_esrc[start + i];
        int s1 = g_esrc[start + i + 1];
        int s2 = g_esrc[start + i + 2];
        int s3 = g_esrc[start + i + 3];
        float4 v0 = *(const float4*)(feat + (size_t)s0 * 128 + lane * 4);
        float4 v1 = *(const float4*)(feat + (size_t)s1 * 128 + lane * 4);
        float4 v2 = *(const float4*)(feat + (size_t)s2 * 128 + lane * 4);
        float4 v3 = *(const float4*)(feat + (size_t)s3 * 128 + lane * 4);
        acc.x += (v0.x + v1.x) + (v2.x + v3.x);
        acc.y += (v0.y + v1.y) + (v2.y + v3.y);
        acc.z += (v0.z + v1.z) + (v2.z + v3.z);
        acc.w += (v0.w + v1.w) + (v2.w + v3.w);
    }
    for (; i < deg; ++i) {
        int s0 = g_esrc[start + i];
        float4 v0 = *(const float4*)(feat + (size_t)s0 * 128 + lane * 4);
        acc.x += v0.x; acc.y += v0.y; acc.z += v0.z; acc.w += v0.w;
    }
    float inv = 1.0f / fmaxf((float)deg, 1.0f);
    if (lane == 0) g_inv[n] = inv;
    acc.x *= inv; acc.y *= inv; acc.z *= inv; acc.w *= inv;

    __nv_bfloat16 h0, l0, h1, l1, h2, l2, h3, l3;
    bf16_split(acc.x, h0, l0); bf16_split(acc.y, h1, l1);
    bf16_split(acc.z, h2, l2); bf16_split(acc.w, h3, l3);
    size_t base = (size_t)n * 256 + lane * 4;
    ((__nv_bfloat162*)(g_ah + base))[0] = __nv_bfloat162(h0, h1);
    ((__nv_bfloat162*)(g_ah + base))[1] = __nv_bfloat162(h2, h3);
    ((__nv_bfloat162*)(g_al + base))[0] = __nv_bfloat162(l0, l1);
    ((__nv_bfloat162*)(g_al + base))[1] = __nv_bfloat162(l2, l3);

    float4 f = *(const float4*)(feat + (size_t)n * 128 + lane * 4);
    bf16_split(f.x, h0, l0); bf16_split(f.y, h1, l1);
    bf16_split(f.z, h2, l2); bf16_split(f.w, h3, l3);
    size_t base2 = (size_t)n * 256 + 128 + lane * 4;
    ((__nv_bfloat162*)(g_ah + base2))[0] = __nv_bfloat162(h0, h1);
    ((__nv_bfloat162*)(g_ah + base2))[1] = __nv_bfloat162(h2, h3);
    ((__nv_bfloat162*)(g_al + base2))[0] = __nv_bfloat162(l0, l1);
    ((__nv_bfloat162*)(g_al + base2))[1] = __nv_bfloat162(l2, l3);
}

// ---------------- pipelined bf16x3 GEMM: C[NN,256] = A @ W^T (+bias) --------
template <int MODE>
__global__ __launch_bounds__(256, 2)
void gs_gemm_pipe(const __nv_bfloat16* __restrict__ Wh,
                  const __nv_bfloat16* __restrict__ Wl,
                  const float* __restrict__ bias,
                  float* __restrict__ C) {
    constexpr int STR = 40;           // bf16 per smem row (32 + 8 pad)
    constexpr int TSZ = 128 * STR;    // elems per tile
    extern __shared__ __nv_bfloat16 sm[];

    const int tid  = threadIdx.x;
    const int lane = tid & 31;
    const int warp = tid >> 5;
    const int wm   = warp >> 1;
    const int wn   = warp & 1;
    const int m0   = blockIdx.x * 128;
    const int n0   = blockIdx.y * 128;

    float c[2][8][4];
    #pragma unroll
    for (int a = 0; a < 2; ++a)
        #pragma unroll
        for (int b = 0; b < 8; ++b)
            #pragma unroll
            for (int k = 0; k < 4; ++k) c[a][b][k] = 0.f;

    auto issue_load = [&](int kt, int st) {
        const int k0 = kt * 32;
        __nv_bfloat16* base = sm + st * 4 * TSZ;
        #pragma unroll
        for (int l = 0; l < 2; ++l) {
            int idx = tid + l * 256;
            int r   = idx >> 2;
            int cq  = (idx & 3) * 8;
            uint32_t ds = smem_u32(base + r * STR + cq);
            cp16(ds,             g_ah + (size_t)(m0 + r) * 256 + k0 + cq);
            cp16(ds + TSZ * 2,   g_al + (size_t)(m0 + r) * 256 + k0 + cq);
            cp16(ds + TSZ * 4,   Wh   + (size_t)(n0 + r) * 256 + k0 + cq);
            cp16(ds + TSZ * 6,   Wl   + (size_t)(n0 + r) * 256 + k0 + cq);
        }
        cp_commit();
    };

    issue_load(0, 0);

    for (int kt = 0; kt < 8; ++kt) {
        const int st = kt & 1;
        cp_wait<0>();
        __syncthreads();
        if (kt + 1 < 8) issue_load(kt + 1, st ^ 1);

        const __nv_bfloat16* Ahs = sm + st * 4 * TSZ;
        const __nv_bfloat16* Als = Ahs + TSZ;
        const __nv_bfloat16* Bhs = Ahs + 2 * TSZ;
        const __nv_bfloat16* Bls = Ahs + 3 * TSZ;

        #pragma unroll
        for (int ks = 0; ks < 2; ++ks) {
            uint32_t ah[2][4], al[2][4];
            #pragma unroll
            for (int mi = 0; mi < 2; ++mi) {
                int r  = wm * 32 + mi * 16 + (lane & 15);
                int cc = ks * 16 + (lane >> 4) * 8;
                ldm_x4(ah[mi], smem_u32(Ahs + r * STR + cc));
                ldm_x4(al[mi], smem_u32(Als + r * STR + cc));
            }
            int mq = lane >> 3, ri = lane & 7;
            #pragma unroll
            for (int nip = 0; nip < 4; ++nip) {
                int row = wn * 64 + nip * 16 + (mq >> 1) * 8 + ri;
                int col = ks * 16 + (mq & 1) * 8;
                uint32_t bh4[4], bl4[4];
                ldm_x4(bh4, smem_u32(Bhs + row * STR + col));
                ldm_x4(bl4, smem_u32(Bls + row * STR + col));
                #pragma unroll
                for (int mi = 0; mi < 2; ++mi) {
                    mma_bf16(c[mi][2 * nip + 0], ah[mi], &bh4[0]);
                    mma_bf16(c[mi][2 * nip + 0], ah[mi], &bl4[0]);
                    mma_bf16(c[mi][2 * nip + 0], al[mi], &bh4[0]);
                    mma_bf16(c[mi][2 * nip + 1], ah[mi], &bh4[2]);
                    mma_bf16(c[mi][2 * nip + 1], ah[mi], &bl4[2]);
                    mma_bf16(c[mi][2 * nip + 1], al[mi], &bh4[2]);
                }
            }
        }
    }

    #pragma unroll
    for (int mi = 0; mi < 2; ++mi) {
        int row = m0 + wm * 32 + mi * 16 + (lane >> 2);
        #pragma unroll
        for (int ni = 0; ni < 8; ++ni) {
            int col = n0 + wn * 64 + ni * 8 + (lane & 3) * 2;
            float2 v0 = make_float2(c[mi][ni][0], c[mi][ni][1]);
            float2 v1 = make_float2(c[mi][ni][2], c[mi][ni][3]);
            if (MODE == 1) {
                float b0 = bias[col], b1 = bias[col + 1];
                v0.x += b0; v0.y += b1;
                v1.x += b0; v1.y += b1;
            }
            if (row < NN)     *(float2*)(C + (size_t)row * 256 + col)       = v0;
            if (row + 8 < NN) *(float2*)(C + (size_t)(row + 8) * 256 + col) = v1;
        }
    }
}

// ---------------- layer-1 epilogue: normalize + relu -> split bf16 ----------
__global__ void gs_norm_relu_split() {
    int t = blockIdx.x * blockDim.x + threadIdx.x;
    int n = t >> 5;
    if (n >= NN) return;
    int lane = t & 31;
    const float* row = g_y + (size_t)n * 256;
    float4 v0 = *(const float4*)(row + lane * 4);
    float4 v1 = *(const float4*)(row + 128 + lane * 4);
    float s = v0.x * v0.x + v0.y * v0.y + v0.z * v0.z + v0.w * v0.w
            + v1.x * v1.x + v1.y * v1.y + v1.z * v1.z + v1.w * v1.w;
    #pragma unroll
    for (int o = 16; o > 0; o >>= 1) s += __shfl_xor_sync(0xffffffffu, s, o);
    float scale = 1.0f / fmaxf(sqrtf(s), 1e-12f);

    float r0 = fmaxf(v0.x * scale, 0.f), r1 = fmaxf(v0.y * scale, 0.f);
    float r2 = fmaxf(v0.z * scale, 0.f), r3 = fmaxf(v0.w * scale, 0.f);
    float r4 = fmaxf(v1.x * scale, 0.f), r5 = fmaxf(v1.y * scale, 0.f);
    float r6 = fmaxf(v1.z * scale, 0.f), r7 = fmaxf(v1.w * scale, 0.f);

    __nv_bfloat16 h0, l0, h1, l1, h2, l2, h3, l3;
    size_t base = (size_t)n * 256 + lane * 4;
    bf16_split(r0, h0, l0); bf16_split(r1, h1, l1);
    bf16_split(r2, h2, l2); bf16_split(r3, h3, l3);
    ((__nv_bfloat162*)(g_ah + base))[0] = __nv_bfloat162(h0, h1);
    ((__nv_bfloat162*)(g_ah + base))[1] = __nv_bfloat162(h2, h3);
    ((__nv_bfloat162*)(g_al + base))[0] = __nv_bfloat162(l0, l1);
    ((__nv_bfloat162*)(g_al + base))[1] = __nv_bfloat162(l2, l3);

    size_t base2 = base + 128;
    bf16_split(r4, h0, l0); bf16_split(r5, h1, l1);
    bf16_split(r6, h2, l2); bf16_split(r7, h3, l3);
    ((__nv_bfloat162*)(g_ah + base2))[0] = __nv_bfloat162(h0, h1);
    ((__nv_bfloat162*)(g_ah + base2))[1] = __nv_bfloat162(h2, h3);
    ((__nv_bfloat162*)(g_al + base2))[0] = __nv_bfloat162(l0, l1);
    ((__nv_bfloat162*)(g_al + base2))[1] = __nv_bfloat162(l2, l3);
}

// ---------------- fused gather2 + final head --------------------------------
__global__ void gs_gather2_final(const float* __restrict__ b2,
                                 const float* __restrict__ Wfc,
                                 const float* __restrict__ bfc,
                                 float* __restrict__ out) {
    int t = blockIdx.x * blockDim.x + threadIdx.x;
    int n = t >> 5;
    if (n >= NN) return;
    int lane = t & 31;
    int start = g_off[n], deg = g_deg[n];

    float4 acc = make_float4(0.f, 0.f, 0.f, 0.f);
    int i = 0;
    for (; i + 4 <= deg; i += 4) {
        int s0 = g_esrc[start + i];
        int s1 = g_esrc[start + i + 1];
        int s2 = g_esrc[start + i + 2];
        int s3 = g_esrc[start + i + 3];
        float4 v0 = *(const float4*)(g_y + (size_t)s0 * 256 + lane * 4);
        float4 v1 = *(const float4*)(g_y + (size_t)s1 * 256 + lane * 4);
        float4 v2 = *(const float4*)(g_y + (size_t)s2 * 256 + lane * 4);
        float4 v3 = *(const float4*)(g_y + (size_t)s3 * 256 + lane * 4);
        acc.x += (v0.x + v1.x) + (v2.x + v3.x);
        acc.y += (v0.y + v1.y) + (v2.y + v3.y);
        acc.z += (v0.z + v1.z) + (v2.z + v3.z);
        acc.w += (v0.w + v1.w) + (v2.w + v3.w);
    }
    for (; i < deg; ++i) {
        int s0 = g_esrc[start + i];
        float4 v0 = *(const float4*)(g_y + (size_t)s0 * 256 + lane * 4);
        acc.x += v0.x; acc.y += v0.y; acc.z += v0.z; acc.w += v0.w;
    }
    float inv = g_inv[n];

    float4 r  = *(const float4*)(g_y + (size_t)n * 256 + 128 + lane * 4);
    float4 bb = *(const float4*)(b2 + lane * 4);
    float4 v;
    v.x = acc.x * inv + r.x + bb.x;
    v.y = acc.y * inv + r.y + bb.y;
    v.z = acc.z * inv + r.z + bb.z;
    v.w = acc.w * inv + r.w + bb.w;

    float s = v.x * v.x + v.y * v.y + v.z * v.z + v.w * v.w;
    #pragma unroll
    for (int o = 16; o > 0; o >>= 1) s += __shfl_xor_sync(0xffffffffu, s, o);
    float scale = 1.0f / fmaxf(sqrtf(s), 1e-12f);
    v.x *= scale; v.y *= scale; v.z *= scale; v.w *= scale;

    float4 w0 = *(const float4*)(Wfc + lane * 4);
    float4 w1 = *(const float4*)(Wfc + 128 + lane * 4);
    float l0 = v.x * w0.x + v.y * w0.y + v.z * w0.z + v.w * w0.w;
    float l1 = v.x * w1.x + v.y * w1.y + v.z * w1.z + v.w * w1.w;
    #pragma unroll
    for (int o = 16; o > 0; o >>= 1) {
        l0 += __shfl_xor_sync(0xffffffffu, l0, o);
        l1 += __shfl_xor_sync(0xffffffffu, l1, o);
    }
    if (lane == 0) {
        l0 += bfc[0]; l1 += bfc[1];
        float m  = fmaxf(l0, l1);
        float e0 = expf(l0 - m), e1 = expf(l1 - m);
        float d  = 1.0f / (e0 + e1);
        out[(size_t)n * 2 + 0] = e0 * d;
        out[(size_t)n * 2 + 1] = e1 * d;
    }
}

// ---------------- launch -----------------------------------------------------
extern "C" void kernel_launch(void* const* d_in, const int* in_sizes, int n_in,
                              void* d_out, int out_size) {
    const float* feat = (const float*)d_in[0];
    const int*   ei   = (const int*)d_in[1];
    const float* W1l  = (const float*)d_in[2];
    const float* b1   = (const float*)d_in[3];
    const float* W1r  = (const float*)d_in[4];
    const float* W2l  = (const float*)d_in[5];
    const float* b2   = (const float*)d_in[6];
    const float* W2r  = (const float*)d_in[7];
    const float* Wfc  = (const float*)d_in[8];
    const float* bfc  = (const float*)d_in[9];
    float* out = (float*)d_out;

    float* p_y;
    cudaGetSymbolAddress((void**)&p_y, g_y);
    __nv_bfloat16 *p_wh1, *p_wl1, *p_wh2, *p_wl2;
    cudaGetSymbolAddress((void**)&p_wh1, g_wh1);
    cudaGetSymbolAddress((void**)&p_wl1, g_wl1);
    cudaGetSymbolAddress((void**)&p_wh2, g_wh2);
    cudaGetSymbolAddress((void**)&p_wl2, g_wl2);

    const int SMEM = 2 * 4 * 128 * 40 * 2;  // 81920 B
    cudaFuncSetAttribute(gs_gemm_pipe<1>, cudaFuncAttributeMaxDynamicSharedMemorySize, SMEM);
    cudaFuncSetAttribute(gs_gemm_pipe<2>, cudaFuncAttributeMaxDynamicSharedMemorySize, SMEM);

    // prologue + CSR build
    gs_init<<<(131072 + 255) / 256, 256>>>(W1l, W1r, W2l, W2r);
    gs_hist<<<(NE / 4 + 255) / 256, 256>>>(ei);
    gs_offs<<<(NN + 255) / 256, 256>>>();
    gs_fill<<<(NE / 4 + 255) / 256, 256>>>(ei);

    // layer 1
    gs_gather1<<<(NN * 32 + 255) / 256, 256>>>(feat);
    {
        dim3 grid((NN + 127) / 128, 2);
        gs_gemm_pipe<1><<<grid, 256, SMEM>>>(p_wh1, p_wl1, b1, p_y);
    }
    gs_norm_relu_split<<<(NN * 32 + 255) / 256, 256>>>();

    // layer 2
    {
        dim3 grid((NN + 127) / 128, 2);
        gs_gemm_pipe<2><<<grid, 256, SMEM>>>(p_wh2, p_wl2, nullptr, p_y);
    }
    gs_gather2_final<<<(NN * 32 + 255) / 256, 256>>>(b2, Wfc, bfc, out);
}